// round 2
// baseline (speedup 1.0000x reference)
#include <cuda_runtime.h>
#include <math.h>

#define Bb 2
#define Nn 4096
#define Kk 32
#define D0 64
#define D1 32
#define HID 32
#define EIN 161
#define E2C 322
#define EIP 168
#define H1P 324

__device__ __forceinline__ float siluf(float x) { return x / (1.f + __expf(-x)); }
__device__ __forceinline__ float sigmf(float x) { return 1.f / (1.f + __expf(-x)); }

__global__ void __launch_bounds__(256)
egnn_kernel(const float* __restrict__ f0, const float* __restrict__ f1,
            const int* __restrict__ nbr, const unsigned char* __restrict__ msk,
            const float* __restrict__ rdist,
            const float* __restrict__ We1, const float* __restrict__ be1,
            const float* __restrict__ We2, const float* __restrict__ be2,
            const float* __restrict__ Wh1, const float* __restrict__ bh1,
            const float* __restrict__ Wh2, const float* __restrict__ bh2,
            const float* __restrict__ Wn1, const float* __restrict__ bn1,
            const float* __restrict__ Wn2, const float* __restrict__ bn2,
            const float* __restrict__ Wg,  const float* __restrict__ bg,
            const float* __restrict__ lng, const float* __restrict__ lnb,
            const float* __restrict__ hns, const float* __restrict__ hnb,
            float* __restrict__ out)
{
    extern __shared__ float sm[];
    float* EI      = sm;                    // [32][168]  edge_in (cols: ni 0-63, nj 64-127, relnorm 128-159, rdist 160)
    float* REL     = EI  + Kk*EIP;          // [32][32][3]
    float* H1      = REL + Kk*96;           // [32][324]  hidden1, later reused for w
    float* WT      = H1  + Kk*H1P;          // [8][322]   W_e1 tile
    float* MS      = WT  + 8*E2C;           // [32][33]   m_ij
    float* G1      = MS  + Kk*33;           // [32][132]  hidden (htype MLP)
    float* nodes_s = G1  + Kk*132;          // [64]
    float* f1i_s   = nodes_s + 64;          // [96]
    float* HT      = f1i_s + 96;            // [96] htype_update
    float* MI      = HT  + 96;              // [32]
    float* NI      = MI  + 32;              // [96] node_in
    float* N1s     = NI  + 96;              // [128]
    float* nouts   = N1s + 128;             // [64]
    float* gates   = nouts + 64;            // [32]
    float* maskv   = gates + 32;            // [32]
    float* stats   = maskv + 32;            // [2]

    const int tid  = threadIdx.x;
    const int lane = tid & 31;
    const int wrow = tid >> 5;               // 0..7
    const int node = blockIdx.x;              // bi*N + ni
    const int bbase = (node / Nn) * Nn;

    // ---- stage node-i features ----
    if (tid < 64)                nodes_s[tid]    = f0[node*64 + tid];
    else if (tid < 160)          f1i_s[tid - 64] = f1[node*96 + (tid - 64)];
    __syncthreads();

    // ---- gather per-edge data (warp w handles edges w, w+8, w+16, w+24) ----
    #pragma unroll
    for (int i = 0; i < 4; i++) {
        const int e = wrow + 8*i;
        const int j = nbr[node*Kk + e];
        const float* f1j = f1 + (size_t)(bbase + j) * 96;
        const float* f0j = f0 + (size_t)(bbase + j) * 64;
        // lane == d (0..31)
        float r0 = f1i_s[lane*3+0] - f1j[lane*3+0];
        float r1 = f1i_s[lane*3+1] - f1j[lane*3+1];
        float r2 = f1i_s[lane*3+2] - f1j[lane*3+2];
        REL[(e*32 + lane)*3 + 0] = r0;
        REL[(e*32 + lane)*3 + 1] = r1;
        REL[(e*32 + lane)*3 + 2] = r2;
        EI[e*EIP + 128 + lane] = sqrtf(r0*r0 + r1*r1 + r2*r2);
        EI[e*EIP +  64 + lane] = f0j[lane];
        EI[e*EIP +  96 + lane] = f0j[lane + 32];
        EI[e*EIP +       lane] = nodes_s[lane];
        EI[e*EIP +  32 + lane] = nodes_s[lane + 32];
        if (lane == 0) {
            EI[e*EIP + 160] = rdist[node*Kk + e];
            maskv[e] = (float)msk[node*Kk + e];
        }
    }
    __syncthreads();

    // ---- GEMM1: H1[32][322] = silu(EI[32][161] @ We1 + be1) ----
    float acc[4][11];
    #pragma unroll
    for (int i = 0; i < 4; i++)
        #pragma unroll
        for (int jj = 0; jj < 11; jj++) acc[i][jj] = 0.f;

    for (int kk = 0; kk < EIN; kk += 8) {
        const int rows = min(8, EIN - kk);
        for (int idx = tid; idx < rows * E2C; idx += 256)
            WT[idx] = We1[(size_t)(kk + idx / E2C) * E2C + (idx % E2C)];
        __syncthreads();
        for (int r = 0; r < rows; r++) {
            float ev0 = EI[(wrow +  0)*EIP + kk + r];
            float ev1 = EI[(wrow +  8)*EIP + kk + r];
            float ev2 = EI[(wrow + 16)*EIP + kk + r];
            float ev3 = EI[(wrow + 24)*EIP + kk + r];
            #pragma unroll
            for (int jj = 0; jj < 11; jj++) {
                const int c = lane + 32*jj;
                if (c < E2C) {
                    float wv = WT[r*E2C + c];
                    acc[0][jj] += ev0 * wv;
                    acc[1][jj] += ev1 * wv;
                    acc[2][jj] += ev2 * wv;
                    acc[3][jj] += ev3 * wv;
                }
            }
        }
        __syncthreads();
    }
    #pragma unroll
    for (int i = 0; i < 4; i++)
        #pragma unroll
        for (int jj = 0; jj < 11; jj++) {
            const int c = lane + 32*jj;
            if (c < E2C) H1[(wrow + 8*i)*H1P + c] = siluf(acc[i][jj] + be1[c]);
        }
    __syncthreads();

    // ---- GEMM2: MS[32][32] = silu(H1 @ We2 + be2) ----
    {
        float a2[4] = {0.f, 0.f, 0.f, 0.f};
        for (int r = 0; r < E2C; r++) {
            float wv = We2[r*32 + lane];
            #pragma unroll
            for (int i = 0; i < 4; i++) a2[i] += H1[(wrow + 8*i)*H1P + r] * wv;
        }
        #pragma unroll
        for (int i = 0; i < 4; i++)
            MS[(wrow + 8*i)*33 + lane] = siluf(a2[i] + be2[lane]);
    }
    __syncthreads();

    // ---- GEMM3: G1[32][128] = silu(MS @ Wh1 + bh1) ----
    {
        float a3[4][4];
        #pragma unroll
        for (int i = 0; i < 4; i++)
            #pragma unroll
            for (int jj = 0; jj < 4; jj++) a3[i][jj] = 0.f;
        for (int r = 0; r < 32; r++) {
            float mv0 = MS[(wrow +  0)*33 + r];
            float mv1 = MS[(wrow +  8)*33 + r];
            float mv2 = MS[(wrow + 16)*33 + r];
            float mv3 = MS[(wrow + 24)*33 + r];
            #pragma unroll
            for (int jj = 0; jj < 4; jj++) {
                float wv = Wh1[r*128 + lane + 32*jj];
                a3[0][jj] += mv0 * wv;
                a3[1][jj] += mv1 * wv;
                a3[2][jj] += mv2 * wv;
                a3[3][jj] += mv3 * wv;
            }
        }
        #pragma unroll
        for (int i = 0; i < 4; i++)
            #pragma unroll
            for (int jj = 0; jj < 4; jj++) {
                const int c = lane + 32*jj;
                G1[(wrow + 8*i)*132 + c] = siluf(a3[i][jj] + bh1[c]);
            }
    }
    __syncthreads();

    // ---- GEMM4: w[32][32] = G1 @ Wh2 + bh2   (stored into H1 rows, reusing smem) ----
    {
        float a4[4] = {0.f, 0.f, 0.f, 0.f};
        for (int r = 0; r < 128; r++) {
            float wv = Wh2[r*32 + lane];
            #pragma unroll
            for (int i = 0; i < 4; i++) a4[i] += G1[(wrow + 8*i)*132 + r] * wv;
        }
        #pragma unroll
        for (int i = 0; i < 4; i++)
            H1[(wrow + 8*i)*H1P + lane] = a4[i] + bh2[lane];
    }
    __syncthreads();

    // ---- htype_update, masked m_i sum, layernorm stats (disjoint thread groups) ----
    if (tid < 96) {
        const int d = tid / 3, m = tid % 3;
        const float hs = hns[d], hb = hnb[d];
        float s = 0.f;
        for (int e = 0; e < 32; e++) {
            float nrm  = EI[e*EIP + 128 + d];
            float coef = (nrm * hs + hb) / fmaxf(nrm, 1e-8f);
            s += REL[(e*32 + d)*3 + m] * coef * H1[e*H1P + d];
        }
        HT[tid] = s;
    } else if (tid < 128) {
        const int c = tid - 96;
        float s = 0.f;
        for (int e = 0; e < 32; e++)
            if (maskv[e] != 0.f) s += MS[e*33 + c];
        MI[c] = s;
    } else if (tid < 160) {
        float x0 = nodes_s[lane], x1 = nodes_s[lane + 32];
        float s = x0 + x1, ss = x0*x0 + x1*x1;
        #pragma unroll
        for (int o = 16; o > 0; o >>= 1) {
            s  += __shfl_down_sync(0xffffffffu, s,  o);
            ss += __shfl_down_sync(0xffffffffu, ss, o);
        }
        if (lane == 0) {
            float mu  = s * (1.f/64.f);
            float var = ss * (1.f/64.f) - mu*mu;
            stats[0] = mu;
            stats[1] = rsqrtf(var + 1e-5f);
        }
    }
    __syncthreads();

    // ---- node_in = [layernorm(nodes), m_i] ----
    if (tid < 64)       NI[tid] = (nodes_s[tid] - stats[0]) * stats[1] * lng[tid] + lnb[tid];
    else if (tid < 96)  NI[tid] = MI[tid - 64];
    __syncthreads();

    // ---- N1[128] = silu(node_in @ Wn1 + bn1) ----
    if (tid < 128) {
        float a = 0.f;
        for (int r = 0; r < 96; r++) a += NI[r] * Wn1[r*128 + tid];
        N1s[tid] = siluf(a + bn1[tid]);
    }
    __syncthreads();

    // ---- node_out[64] = N1 @ Wn2 + bn2 + nodes ----
    if (tid < 64) {
        float a = 0.f;
        for (int r = 0; r < 128; r++) a += N1s[r] * Wn2[r*64 + tid];
        float v = a + bn2[tid] + nodes_s[tid];
        nouts[tid] = v;
        out[(size_t)node*64 + tid] = v;
    }
    __syncthreads();

    // ---- gate[32] = sigmoid(node_out @ Wg + bg) ----
    if (tid < 32) {
        float a = 0.f;
        for (int r = 0; r < 64; r++) a += nouts[r] * Wg[r*32 + tid];
        gates[tid] = sigmf(a + bg[tid]);
    }
    __syncthreads();

    // ---- f1_out = (features1 + htype_update) * gate ----
    if (tid < 96) {
        const int d = tid / 3;
        float v = (f1i_s[tid] + HT[tid]) * gates[d];
        out[(size_t)Bb*Nn*D0 + (size_t)node*96 + tid] = v;
    }
}

extern "C" void kernel_launch(void* const* d_in, const int* in_sizes, int n_in,
                              void* d_out, int out_size) {
    const float* f0   = (const float*)d_in[0];
    const float* f1   = (const float*)d_in[1];
    const int*   nbr  = (const int*)d_in[2];
    const unsigned char* msk = (const unsigned char*)d_in[3];
    const float* rdist= (const float*)d_in[4];
    const float* We1  = (const float*)d_in[5];
    const float* be1  = (const float*)d_in[6];
    const float* We2  = (const float*)d_in[7];
    const float* be2  = (const float*)d_in[8];
    const float* Wh1  = (const float*)d_in[9];
    const float* bh1  = (const float*)d_in[10];
    const float* Wh2  = (const float*)d_in[11];
    const float* bh2  = (const float*)d_in[12];
    const float* Wn1  = (const float*)d_in[13];
    const float* bn1  = (const float*)d_in[14];
    const float* Wn2  = (const float*)d_in[15];
    const float* bn2  = (const float*)d_in[16];
    const float* Wg   = (const float*)d_in[17];
    const float* bg   = (const float*)d_in[18];
    const float* lng  = (const float*)d_in[19];
    const float* lnb  = (const float*)d_in[20];
    const float* hns  = (const float*)d_in[21];
    const float* hnb  = (const float*)d_in[22];
    float* out = (float*)d_out;

    const size_t smem_floats =
        (size_t)Kk*EIP + Kk*96 + (size_t)Kk*H1P + 8*E2C + Kk*33 + Kk*132 +
        64 + 96 + 96 + 32 + 96 + 128 + 64 + 32 + 32 + 2;
    const size_t smem_bytes = smem_floats * sizeof(float);

    cudaFuncSetAttribute(egnn_kernel, cudaFuncAttributeMaxDynamicSharedMemorySize,
                         (int)smem_bytes);

    egnn_kernel<<<Bb*Nn, 256, smem_bytes>>>(
        f0, f1, nbr, msk, rdist,
        We1, be1, We2, be2, Wh1, bh1, Wh2, bh2,
        Wn1, bn1, Wn2, bn2, Wg, bg, lng, lnb, hns, hnb, out);
}

// round 3
// speedup vs baseline: 1.2891x; 1.2891x over previous
#include <cuda_runtime.h>
#include <math.h>

#define Bb 2
#define Nn 4096
#define NT (Bb*Nn)
#define Kk 32
#define D0 64
#define D1 32
#define HID 32
#define EIN 161
#define E2C 322
#define W1P 352        // padded width of W1 tail tile / PI
#define H1P 328        // padded H1 row stride (mult of 4)
#define G1P 136
#define MSP 36

__device__ float PI_g[(size_t)NT * E2C + 384];
__device__ float PJ_g[(size_t)NT * E2C + 384];

__device__ __forceinline__ float siluf(float x) { return x / (1.f + __expf(-x)); }
__device__ __forceinline__ float sigmf(float x) { return 1.f / (1.f + __expf(-x)); }

// ---------------- per-node projections: PI = nodes @ We1[0:64] + be1, PJ = nodes @ We1[64:128]
__global__ void __launch_bounds__(256)
proj_kernel(const float* __restrict__ f0, const float* __restrict__ We1,
            const float* __restrict__ be1)
{
    __shared__ float nd[32][65];
    const int nb = blockIdx.x * 32;
    const int tid = threadIdx.x;
    for (int idx = tid; idx < 32 * 64; idx += 256)
        nd[idx >> 6][idx & 63] = f0[(size_t)nb * 64 + idx];
    __syncthreads();
    for (int idx = tid; idx < 32 * E2C; idx += 256) {
        const int n = idx / E2C;
        const int c = idx - n * E2C;
        float si = 0.f, sj = 0.f;
        #pragma unroll 8
        for (int d = 0; d < 64; d++) {
            const float v = nd[n][d];
            si += v * __ldg(&We1[d * E2C + c]);
            sj += v * __ldg(&We1[(64 + d) * E2C + c]);
        }
        PI_g[(size_t)(nb + n) * E2C + c] = si + be1[c];
        PJ_g[(size_t)(nb + n) * E2C + c] = sj;
    }
}

// ---------------- main fused kernel: one block per node
__global__ void __launch_bounds__(256)
egnn_main(const float* __restrict__ f0, const float* __restrict__ f1,
          const int* __restrict__ nbr, const unsigned char* __restrict__ msk,
          const float* __restrict__ rdist,
          const float* __restrict__ We1,
          const float* __restrict__ We2, const float* __restrict__ be2,
          const float* __restrict__ Wh1, const float* __restrict__ bh1,
          const float* __restrict__ Wh2, const float* __restrict__ bh2,
          const float* __restrict__ Wn1, const float* __restrict__ bn1,
          const float* __restrict__ Wn2, const float* __restrict__ bn2,
          const float* __restrict__ Wg,  const float* __restrict__ bg,
          const float* __restrict__ lng, const float* __restrict__ lnb,
          const float* __restrict__ hns, const float* __restrict__ hnb,
          float* __restrict__ out)
{
    extern __shared__ float sm[];
    float* W1s     = sm;                       // [33][352] We1 rows 128..160 (zero-padded); later aliased by G1 [32][136]
    float* H1      = W1s + 33 * W1P;           // [32][328]
    float* EIc     = H1 + 32 * H1P;            // [32][36]  cols 0..31 rel_norm, col 32 rdist
    float* PI      = EIc + 32 * MSP;           // [352]
    float* MS      = PI + W1P;                 // [32][36]
    float* nodes_s = MS + 32 * MSP;            // [64]
    float* f1i_s   = nodes_s + 64;             // [96]
    float* HT      = f1i_s + 96;               // [96]
    float* MI      = HT + 96;                  // [32]
    float* NI      = MI + 32;                  // [96]
    float* N1s     = NI + 96;                  // [128]
    float* nouts   = N1s + 128;                // [64]
    float* gates   = nouts + 64;               // [32]
    float* maskv   = gates + 32;               // [32]
    float* stats   = maskv + 32;               // [2]
    int*   nbr_s   = (int*)(stats + 2);        // [32]
    float* G1      = W1s;                      // alias (W1s dead after GEMM1)

    const int tid  = threadIdx.x;
    const int lane = tid & 31;
    const int wrow = tid >> 5;
    const int node = blockIdx.x;
    const int bbase = (node / Nn) * Nn;

    // ---- stage node-i features + PI + W1s tail tile ----
    if (tid < 64)           nodes_s[tid]    = f0[(size_t)node * 64 + tid];
    else if (tid < 160)     f1i_s[tid - 64] = f1[(size_t)node * 96 + (tid - 64)];
    for (int c = tid; c < W1P; c += 256)
        PI[c] = (c < E2C) ? PI_g[(size_t)node * E2C + c] : 0.f;
    for (int row = wrow; row < 33; row += 8)
        for (int c = lane; c < W1P; c += 32)
            W1s[row * W1P + c] = (c < E2C) ? __ldg(&We1[(size_t)(128 + row) * E2C + c]) : 0.f;
    __syncthreads();

    // ---- gather per-edge rel_norm / rdist / mask ----
    #pragma unroll
    for (int i = 0; i < 4; i++) {
        const int e = wrow + 8 * i;
        const int j = nbr[node * Kk + e];
        const float* f1j = f1 + (size_t)(bbase + j) * 96;
        const float r0 = f1i_s[lane * 3 + 0] - f1j[lane * 3 + 0];
        const float r1 = f1i_s[lane * 3 + 1] - f1j[lane * 3 + 1];
        const float r2 = f1i_s[lane * 3 + 2] - f1j[lane * 3 + 2];
        EIc[e * MSP + lane] = sqrtf(r0 * r0 + r1 * r1 + r2 * r2);
        if (lane == 0) {
            EIc[e * MSP + 32] = rdist[node * Kk + e];
            maskv[e] = (float)msk[node * Kk + e];
            nbr_s[e] = j;
        }
    }
    __syncthreads();

    // ---- GEMM1 (K=33): acc = [rel_norm,rdist] @ W1s ----
    float acc[4][11];
    #pragma unroll
    for (int i = 0; i < 4; i++)
        #pragma unroll
        for (int jj = 0; jj < 11; jj++) acc[i][jj] = 0.f;

    #pragma unroll 3
    for (int k = 0; k < 33; k++) {
        const float ev0 = EIc[(wrow +  0) * MSP + k];
        const float ev1 = EIc[(wrow +  8) * MSP + k];
        const float ev2 = EIc[(wrow + 16) * MSP + k];
        const float ev3 = EIc[(wrow + 24) * MSP + k];
        #pragma unroll
        for (int jj = 0; jj < 11; jj++) {
            const float wv = W1s[k * W1P + lane + 32 * jj];
            acc[0][jj] += ev0 * wv;
            acc[1][jj] += ev1 * wv;
            acc[2][jj] += ev2 * wv;
            acc[3][jj] += ev3 * wv;
        }
    }
    // epilogue: add PI + gathered PJ, silu, store H1
    #pragma unroll
    for (int i = 0; i < 4; i++) {
        const int e = wrow + 8 * i;
        const float* pj = PJ_g + (size_t)(bbase + nbr_s[e]) * E2C;
        #pragma unroll
        for (int jj = 0; jj < 11; jj++) {
            const int c = lane + 32 * jj;
            if (c < E2C)
                H1[e * H1P + c] = siluf(acc[i][jj] + PI[c] + __ldg(pj + c));
        }
    }
    __syncthreads();

    // ---- GEMM2: MS[32][32] = silu(H1[32][322] @ We2 + be2) ----
    {
        float a2[4] = {0.f, 0.f, 0.f, 0.f};
        for (int r = 0; r < 320; r += 4) {
            const float w0 = __ldg(&We2[(r + 0) * 32 + lane]);
            const float w1 = __ldg(&We2[(r + 1) * 32 + lane]);
            const float w2 = __ldg(&We2[(r + 2) * 32 + lane]);
            const float w3 = __ldg(&We2[(r + 3) * 32 + lane]);
            #pragma unroll
            for (int i = 0; i < 4; i++) {
                const float4 h = *(const float4*)&H1[(wrow + 8 * i) * H1P + r];
                a2[i] += h.x * w0 + h.y * w1 + h.z * w2 + h.w * w3;
            }
        }
        #pragma unroll
        for (int r = 320; r < 322; r++) {
            const float wv = __ldg(&We2[r * 32 + lane]);
            #pragma unroll
            for (int i = 0; i < 4; i++)
                a2[i] += H1[(wrow + 8 * i) * H1P + r] * wv;
        }
        #pragma unroll
        for (int i = 0; i < 4; i++)
            MS[(wrow + 8 * i) * MSP + lane] = siluf(a2[i] + be2[lane]);
    }
    __syncthreads();

    // ---- GEMM3: G1[32][128] = silu(MS @ Wh1 + bh1)   (G1 aliases dead W1s) ----
    {
        float a3[4][4];
        #pragma unroll
        for (int i = 0; i < 4; i++)
            #pragma unroll
            for (int jj = 0; jj < 4; jj++) a3[i][jj] = 0.f;
        for (int r = 0; r < 32; r += 4) {
            float4 m[4];
            #pragma unroll
            for (int i = 0; i < 4; i++)
                m[i] = *(const float4*)&MS[(wrow + 8 * i) * MSP + r];
            #pragma unroll
            for (int q = 0; q < 4; q++) {
                #pragma unroll
                for (int jj = 0; jj < 4; jj++) {
                    const float wv = __ldg(&Wh1[(r + q) * 128 + lane + 32 * jj]);
                    const float mv0 = (q == 0) ? m[0].x : (q == 1) ? m[0].y : (q == 2) ? m[0].z : m[0].w;
                    const float mv1 = (q == 0) ? m[1].x : (q == 1) ? m[1].y : (q == 2) ? m[1].z : m[1].w;
                    const float mv2 = (q == 0) ? m[2].x : (q == 1) ? m[2].y : (q == 2) ? m[2].z : m[2].w;
                    const float mv3 = (q == 0) ? m[3].x : (q == 1) ? m[3].y : (q == 2) ? m[3].z : m[3].w;
                    a3[0][jj] += mv0 * wv;
                    a3[1][jj] += mv1 * wv;
                    a3[2][jj] += mv2 * wv;
                    a3[3][jj] += mv3 * wv;
                }
            }
        }
        #pragma unroll
        for (int i = 0; i < 4; i++)
            #pragma unroll
            for (int jj = 0; jj < 4; jj++) {
                const int c = lane + 32 * jj;
                G1[(wrow + 8 * i) * G1P + c] = siluf(a3[i][jj] + bh1[c]);
            }
    }
    __syncthreads();

    // ---- GEMM4: w[32][32] = G1 @ Wh2 + bh2  (stored into H1 cols 0..31) ----
    {
        float a4[4] = {0.f, 0.f, 0.f, 0.f};
        for (int r = 0; r < 128; r += 4) {
            const float w0 = __ldg(&Wh2[(r + 0) * 32 + lane]);
            const float w1 = __ldg(&Wh2[(r + 1) * 32 + lane]);
            const float w2 = __ldg(&Wh2[(r + 2) * 32 + lane]);
            const float w3 = __ldg(&Wh2[(r + 3) * 32 + lane]);
            #pragma unroll
            for (int i = 0; i < 4; i++) {
                const float4 g = *(const float4*)&G1[(wrow + 8 * i) * G1P + r];
                a4[i] += g.x * w0 + g.y * w1 + g.z * w2 + g.w * w3;
            }
        }
        #pragma unroll
        for (int i = 0; i < 4; i++)
            H1[(wrow + 8 * i) * H1P + lane] = a4[i] + bh2[lane];
    }
    __syncthreads();

    // ---- htype_update (rel recomputed from gmem), masked m_i sum, layernorm stats ----
    if (tid < 96) {
        const int d = tid / 3;
        const float hs = hns[d], hb = hnb[d];
        const float fi = f1i_s[tid];
        float s = 0.f;
        for (int e = 0; e < 32; e++) {
            const float nrm  = EIc[e * MSP + d];
            const float coef = __fdividef(nrm * hs + hb, fmaxf(nrm, 1e-8f));
            const float relv = fi - __ldg(&f1[(size_t)(bbase + nbr_s[e]) * 96 + tid]);
            s += relv * coef * H1[e * H1P + d];
        }
        HT[tid] = s;
    } else if (tid < 128) {
        const int c = tid - 96;
        float s = 0.f;
        for (int e = 0; e < 32; e++)
            if (maskv[e] != 0.f) s += MS[e * MSP + c];
        MI[c] = s;
    } else if (tid < 160) {
        float x0 = nodes_s[lane], x1 = nodes_s[lane + 32];
        float s = x0 + x1, ss = x0 * x0 + x1 * x1;
        #pragma unroll
        for (int o = 16; o > 0; o >>= 1) {
            s  += __shfl_down_sync(0xffffffffu, s,  o);
            ss += __shfl_down_sync(0xffffffffu, ss, o);
        }
        if (lane == 0) {
            const float mu  = s * (1.f / 64.f);
            const float var = ss * (1.f / 64.f) - mu * mu;
            stats[0] = mu;
            stats[1] = rsqrtf(var + 1e-5f);
        }
    }
    __syncthreads();

    // ---- node_in = [layernorm(nodes), m_i] ----
    if (tid < 64)       NI[tid] = (nodes_s[tid] - stats[0]) * stats[1] * lng[tid] + lnb[tid];
    else if (tid < 96)  NI[tid] = MI[tid - 64];
    __syncthreads();

    // ---- N1[128] = silu(node_in @ Wn1 + bn1) ----
    if (tid < 128) {
        float a = 0.f;
        for (int r = 0; r < 96; r++) a += NI[r] * __ldg(&Wn1[r * 128 + tid]);
        N1s[tid] = siluf(a + bn1[tid]);
    }
    __syncthreads();

    // ---- node_out[64] = N1 @ Wn2 + bn2 + nodes ----
    if (tid < 64) {
        float a = 0.f;
        for (int r = 0; r < 128; r++) a += N1s[r] * __ldg(&Wn2[r * 64 + tid]);
        const float v = a + bn2[tid] + nodes_s[tid];
        nouts[tid] = v;
        out[(size_t)node * 64 + tid] = v;
    }
    __syncthreads();

    // ---- gate[32] = sigmoid(node_out @ Wg + bg) ----
    if (tid < 32) {
        float a = 0.f;
        for (int r = 0; r < 64; r++) a += nouts[r] * __ldg(&Wg[r * 32 + tid]);
        gates[tid] = sigmf(a + bg[tid]);
    }
    __syncthreads();

    // ---- f1_out = (features1 + htype_update) * gate ----
    if (tid < 96) {
        const int d = tid / 3;
        const float v = (f1i_s[tid] + HT[tid]) * gates[d];
        out[(size_t)Bb * Nn * D0 + (size_t)node * 96 + tid] = v;
    }
}

extern "C" void kernel_launch(void* const* d_in, const int* in_sizes, int n_in,
                              void* d_out, int out_size) {
    const float* f0   = (const float*)d_in[0];
    const float* f1   = (const float*)d_in[1];
    const int*   nbr  = (const int*)d_in[2];
    const unsigned char* msk = (const unsigned char*)d_in[3];
    const float* rdist= (const float*)d_in[4];
    const float* We1  = (const float*)d_in[5];
    const float* be1  = (const float*)d_in[6];
    const float* We2  = (const float*)d_in[7];
    const float* be2  = (const float*)d_in[8];
    const float* Wh1  = (const float*)d_in[9];
    const float* bh1  = (const float*)d_in[10];
    const float* Wh2  = (const float*)d_in[11];
    const float* bh2  = (const float*)d_in[12];
    const float* Wn1  = (const float*)d_in[13];
    const float* bn1  = (const float*)d_in[14];
    const float* Wn2  = (const float*)d_in[15];
    const float* bn2  = (const float*)d_in[16];
    const float* Wg   = (const float*)d_in[17];
    const float* bg   = (const float*)d_in[18];
    const float* lng  = (const float*)d_in[19];
    const float* lnb  = (const float*)d_in[20];
    const float* hns  = (const float*)d_in[21];
    const float* hnb  = (const float*)d_in[22];
    float* out = (float*)d_out;

    proj_kernel<<<NT / 32, 256>>>(f0, We1, be1);

    const size_t smem_floats =
        (size_t)33 * W1P + 32 * H1P + 32 * MSP + W1P + 32 * MSP +
        64 + 96 + 96 + 32 + 96 + 128 + 64 + 32 + 32 + 2 + 32;
    const size_t smem_bytes = smem_floats * sizeof(float);

    cudaFuncSetAttribute(egnn_main, cudaFuncAttributeMaxDynamicSharedMemorySize,
                         (int)smem_bytes);

    egnn_main<<<NT, 256, smem_bytes>>>(
        f0, f1, nbr, msk, rdist, We1,
        We2, be2, Wh1, bh1, Wh2, bh2,
        Wn1, bn1, Wn2, bn2, Wg, bg, lng, lnb, hns, hnb, out);
}

// round 4
// speedup vs baseline: 1.4492x; 1.1242x over previous
#include <cuda_runtime.h>
#include <math.h>

#define Bb 2
#define Nn 4096
#define NT (Bb*Nn)
#define Kk 32
#define D0 64
#define D1 32
#define EIN 161
#define E2C 322
#define W1P 352        // padded width of W1 tail tile / PI
#define H1P 328        // padded H1 row stride (mult of 4)
#define MSP 36
#define AREG 11616     // 33*352 floats: W1s -> We2s -> (Wh1s|Wh2s)

__device__ float PI_g[(size_t)NT * E2C + 384];
__device__ float PJ_g[(size_t)NT * E2C + 384];

__device__ __forceinline__ float siluf(float x) { return x / (1.f + __expf(-x)); }
__device__ __forceinline__ float sigmf(float x) { return 1.f / (1.f + __expf(-x)); }

// ---------------- per-node projections: PI = nodes @ We1[0:64] + be1, PJ = nodes @ We1[64:128]
__global__ void __launch_bounds__(256)
proj_kernel(const float* __restrict__ f0, const float* __restrict__ We1,
            const float* __restrict__ be1)
{
    __shared__ float nd[16][65];
    const int nb = blockIdx.x * 16;
    const int tid = threadIdx.x;
    for (int idx = tid; idx < 16 * 64; idx += 256)
        nd[idx >> 6][idx & 63] = f0[(size_t)nb * 64 + idx];
    __syncthreads();
    for (int idx = tid; idx < 16 * E2C; idx += 256) {
        const int n = idx / E2C;
        const int c = idx - n * E2C;
        float si = 0.f, sj = 0.f;
        #pragma unroll 8
        for (int d = 0; d < 64; d++) {
            const float v = nd[n][d];
            si += v * __ldg(&We1[d * E2C + c]);
            sj += v * __ldg(&We1[(64 + d) * E2C + c]);
        }
        PI_g[(size_t)(nb + n) * E2C + c] = si + be1[c];
        PJ_g[(size_t)(nb + n) * E2C + c] = sj;
    }
}

// ---------------- main fused kernel: one block per node
__global__ void __launch_bounds__(256)
egnn_main(const float* __restrict__ f0, const float* __restrict__ f1,
          const int* __restrict__ nbr, const unsigned char* __restrict__ msk,
          const float* __restrict__ rdist,
          const float* __restrict__ We1,
          const float* __restrict__ We2, const float* __restrict__ be2,
          const float* __restrict__ Wh1, const float* __restrict__ bh1,
          const float* __restrict__ Wh2, const float* __restrict__ bh2,
          const float* __restrict__ Wn1, const float* __restrict__ bn1,
          const float* __restrict__ Wn2, const float* __restrict__ bn2,
          const float* __restrict__ Wg,  const float* __restrict__ bg,
          const float* __restrict__ lng, const float* __restrict__ lnb,
          const float* __restrict__ hns, const float* __restrict__ hnb,
          float* __restrict__ out)
{
    extern __shared__ float sm[];
    float* A       = sm;                       // AREG floats: W1s, then We2s, then Wh1s|Wh2s
    float* H1      = A + AREG;                 // [32][328]; later aliased by G1 [32][136]
    float* EIc     = H1 + 32 * H1P;            // [32][36]  cols 0..31 rel_norm, col 32 rdist
    float* PI      = EIc + 32 * MSP;           // [352]
    float* MS      = PI + W1P;                 // [32][36]
    float* WS      = MS + 32 * MSP;            // [32][33]  w (GEMM4 out)
    float* HT2     = WS + 32 * 33;             // [192] two htype half-sums
    float* nodes_s = HT2 + 192;                // [64]
    float* f1i_s   = nodes_s + 64;             // [96]
    float* MI      = f1i_s + 96;               // [32]
    float* NI      = MI + 32;                  // [96]
    float* N1s     = NI + 96;                  // [128]
    float* nouts   = N1s + 128;                // [64]
    float* gates   = nouts + 64;               // [32]
    float* maskv   = gates + 32;               // [32]
    float* stats   = maskv + 32;               // [2]
    int*   nbr_s   = (int*)(stats + 2);        // [32]
    float* G1      = H1;                       // alias: G1 [32][136] lives in dead H1
    const int G1P  = 136;

    const int tid  = threadIdx.x;
    const int lane = tid & 31;
    const int wrow = tid >> 5;
    const int node = blockIdx.x;
    const int bbase = (node / Nn) * Nn;

    // ---- stage node-i features + PI + W1s (We1 rows 128..160, zero-padded) ----
    if (tid < 64)           nodes_s[tid]    = f0[(size_t)node * 64 + tid];
    else if (tid < 160)     f1i_s[tid - 64] = f1[(size_t)node * 96 + (tid - 64)];
    for (int c = tid; c < W1P; c += 256)
        PI[c] = (c < E2C) ? PI_g[(size_t)node * E2C + c] : 0.f;
    for (int row = wrow; row < 33; row += 8)
        for (int c = lane; c < W1P; c += 32)
            A[row * W1P + c] = (c < E2C) ? __ldg(&We1[(size_t)(128 + row) * E2C + c]) : 0.f;
    __syncthreads();

    // ---- gather per-edge rel_norm / rdist / mask ----
    #pragma unroll
    for (int i = 0; i < 4; i++) {
        const int e = wrow + 8 * i;
        const int j = nbr[node * Kk + e];
        const float* f1j = f1 + (size_t)(bbase + j) * 96;
        const float r0 = f1i_s[lane * 3 + 0] - f1j[lane * 3 + 0];
        const float r1 = f1i_s[lane * 3 + 1] - f1j[lane * 3 + 1];
        const float r2 = f1i_s[lane * 3 + 2] - f1j[lane * 3 + 2];
        EIc[e * MSP + lane] = sqrtf(r0 * r0 + r1 * r1 + r2 * r2);
        if (lane == 0) {
            EIc[e * MSP + 32] = rdist[node * Kk + e];
            maskv[e] = (float)msk[node * Kk + e];
            nbr_s[e] = j;
        }
    }
    __syncthreads();

    // ---- GEMM1 (K=33): acc = [rel_norm,rdist] @ W1s ----
    float acc[4][11];
    #pragma unroll
    for (int i = 0; i < 4; i++)
        #pragma unroll
        for (int jj = 0; jj < 11; jj++) acc[i][jj] = 0.f;

    #pragma unroll 3
    for (int k = 0; k < 33; k++) {
        const float ev0 = EIc[(wrow +  0) * MSP + k];
        const float ev1 = EIc[(wrow +  8) * MSP + k];
        const float ev2 = EIc[(wrow + 16) * MSP + k];
        const float ev3 = EIc[(wrow + 24) * MSP + k];
        #pragma unroll
        for (int jj = 0; jj < 11; jj++) {
            const float wv = A[k * W1P + lane + 32 * jj];
            acc[0][jj] += ev0 * wv;
            acc[1][jj] += ev1 * wv;
            acc[2][jj] += ev2 * wv;
            acc[3][jj] += ev3 * wv;
        }
    }
    __syncthreads();   // all reads of W1s (region A) done

    // ---- epilogue (PI + PJ gather + silu -> H1), overlapped with We2 staging into A ----
    #pragma unroll
    for (int i = 0; i < 4; i++) {
        const int e = wrow + 8 * i;
        const float* pj = PJ_g + (size_t)(bbase + nbr_s[e]) * E2C;
        #pragma unroll
        for (int jj = 0; jj < 11; jj++) {
            const int c = lane + 32 * jj;
            if (c < E2C)
                H1[e * H1P + c] = siluf(acc[i][jj] + PI[c] + __ldg(pj + c));
        }
    }
    // stage We2 (322*32 floats = 2576 float4) into A
    {
        const float4* src = (const float4*)We2;
        float4* dst = (float4*)A;
        for (int idx = tid; idx < (E2C * 32) / 4; idx += 256)
            dst[idx] = __ldg(&src[idx]);
    }
    __syncthreads();

    // ---- GEMM2: MS[32][32] = silu(H1[32][322] @ We2s + be2) ----
    {
        const float* We2s = A;
        float a2[4] = {0.f, 0.f, 0.f, 0.f};
        for (int r = 0; r < 320; r += 4) {
            const float w0 = We2s[(r + 0) * 32 + lane];
            const float w1 = We2s[(r + 1) * 32 + lane];
            const float w2 = We2s[(r + 2) * 32 + lane];
            const float w3 = We2s[(r + 3) * 32 + lane];
            #pragma unroll
            for (int i = 0; i < 4; i++) {
                const float4 h = *(const float4*)&H1[(wrow + 8 * i) * H1P + r];
                a2[i] += h.x * w0 + h.y * w1 + h.z * w2 + h.w * w3;
            }
        }
        #pragma unroll
        for (int r = 320; r < 322; r++) {
            const float wv = We2s[r * 32 + lane];
            #pragma unroll
            for (int i = 0; i < 4; i++)
                a2[i] += H1[(wrow + 8 * i) * H1P + r] * wv;
        }
        #pragma unroll
        for (int i = 0; i < 4; i++)
            MS[(wrow + 8 * i) * MSP + lane] = siluf(a2[i] + be2[lane]);
    }
    __syncthreads();   // We2s reads done, MS written

    // ---- stage Wh1 (4096 floats) and Wh2 (4096 floats) into A ----
    {
        const float4* s1 = (const float4*)Wh1;
        const float4* s2 = (const float4*)Wh2;
        float4* d1 = (float4*)A;
        float4* d2 = (float4*)(A + 4096);
        for (int idx = tid; idx < 1024; idx += 256) {
            d1[idx] = __ldg(&s1[idx]);
            d2[idx] = __ldg(&s2[idx]);
        }
    }
    __syncthreads();

    // ---- GEMM3: G1[32][128] = silu(MS @ Wh1s + bh1)   (G1 aliases dead H1) ----
    {
        const float* Wh1s = A;
        float a3[4][4];
        #pragma unroll
        for (int i = 0; i < 4; i++)
            #pragma unroll
            for (int jj = 0; jj < 4; jj++) a3[i][jj] = 0.f;
        #pragma unroll 4
        for (int r = 0; r < 32; r++) {
            const float mv0 = MS[(wrow +  0) * MSP + r];
            const float mv1 = MS[(wrow +  8) * MSP + r];
            const float mv2 = MS[(wrow + 16) * MSP + r];
            const float mv3 = MS[(wrow + 24) * MSP + r];
            #pragma unroll
            for (int jj = 0; jj < 4; jj++) {
                const float wv = Wh1s[r * 128 + lane + 32 * jj];
                a3[0][jj] += mv0 * wv;
                a3[1][jj] += mv1 * wv;
                a3[2][jj] += mv2 * wv;
                a3[3][jj] += mv3 * wv;
            }
        }
        #pragma unroll
        for (int i = 0; i < 4; i++)
            #pragma unroll
            for (int jj = 0; jj < 4; jj++) {
                const int c = lane + 32 * jj;
                G1[(wrow + 8 * i) * G1P + c] = siluf(a3[i][jj] + bh1[c]);
            }
    }
    __syncthreads();

    // ---- GEMM4: WS[32][32] = G1 @ Wh2s + bh2 ----
    {
        const float* Wh2s = A + 4096;
        float a4[4] = {0.f, 0.f, 0.f, 0.f};
        for (int r = 0; r < 128; r += 4) {
            const float w0 = Wh2s[(r + 0) * 32 + lane];
            const float w1 = Wh2s[(r + 1) * 32 + lane];
            const float w2 = Wh2s[(r + 2) * 32 + lane];
            const float w3 = Wh2s[(r + 3) * 32 + lane];
            #pragma unroll
            for (int i = 0; i < 4; i++) {
                const float4 g = *(const float4*)&G1[(wrow + 8 * i) * G1P + r];
                a4[i] += g.x * w0 + g.y * w1 + g.z * w2 + g.w * w3;
            }
        }
        #pragma unroll
        for (int i = 0; i < 4; i++)
            WS[(wrow + 8 * i) * 33 + lane] = a4[i] + bh2[lane];
    }
    __syncthreads();

    // ---- htype_update (warps 0-5, two e-halves), masked m_i (warp 6), LN stats (warp 7) ----
    if (tid < 192) {
        const int half = (tid >= 96);
        const int t = tid - 96 * half;
        const int d = t / 3;
        const float hs = hns[d], hb = hnb[d];
        const float fi = f1i_s[t];
        const int e0 = half * 16;
        float s = 0.f;
        #pragma unroll 4
        for (int e = e0; e < e0 + 16; e++) {
            const float nrm  = EIc[e * MSP + d];
            const float coef = __fdividef(nrm * hs + hb, fmaxf(nrm, 1e-8f));
            const float relv = fi - __ldg(&f1[(size_t)(bbase + nbr_s[e]) * 96 + t]);
            s += relv * coef * WS[e * 33 + d];
        }
        HT2[tid] = s;
    } else if (tid < 224) {
        const int c = tid - 192;
        float s = 0.f;
        #pragma unroll 8
        for (int e = 0; e < 32; e++)
            s += maskv[e] * MS[e * MSP + c];
        MI[c] = s;
    } else {
        float x0 = nodes_s[lane], x1 = nodes_s[lane + 32];
        float s = x0 + x1, ss = x0 * x0 + x1 * x1;
        #pragma unroll
        for (int o = 16; o > 0; o >>= 1) {
            s  += __shfl_down_sync(0xffffffffu, s,  o);
            ss += __shfl_down_sync(0xffffffffu, ss, o);
        }
        if (lane == 0) {
            const float mu  = s * (1.f / 64.f);
            const float var = ss * (1.f / 64.f) - mu * mu;
            stats[0] = mu;
            stats[1] = rsqrtf(var + 1e-5f);
        }
    }
    __syncthreads();

    // ---- node_in = [layernorm(nodes), m_i] ----
    if (tid < 64)       NI[tid] = (nodes_s[tid] - stats[0]) * stats[1] * lng[tid] + lnb[tid];
    else if (tid < 96)  NI[tid] = MI[tid - 64];
    __syncthreads();

    // ---- N1[128] = silu(node_in @ Wn1 + bn1) ----
    if (tid < 128) {
        float a = 0.f;
        #pragma unroll 8
        for (int r = 0; r < 96; r++) a += NI[r] * __ldg(&Wn1[r * 128 + tid]);
        N1s[tid] = siluf(a + bn1[tid]);
    }
    __syncthreads();

    // ---- node_out[64] = N1 @ Wn2 + bn2 + nodes ----
    if (tid < 64) {
        float a = 0.f;
        #pragma unroll 8
        for (int r = 0; r < 128; r++) a += N1s[r] * __ldg(&Wn2[r * 64 + tid]);
        const float v = a + bn2[tid] + nodes_s[tid];
        nouts[tid] = v;
        out[(size_t)node * 64 + tid] = v;
    }
    __syncthreads();

    // ---- gate[32] = sigmoid(node_out @ Wg + bg) ----
    if (tid < 32) {
        float a = 0.f;
        #pragma unroll 8
        for (int r = 0; r < 64; r++) a += nouts[r] * __ldg(&Wg[r * 32 + tid]);
        gates[tid] = sigmf(a + bg[tid]);
    }
    __syncthreads();

    // ---- f1_out = (features1 + htype_update) * gate ----
    if (tid < 96) {
        const int d = tid / 3;
        const float v = (f1i_s[tid] + HT2[tid] + HT2[96 + tid]) * gates[d];
        out[(size_t)Bb * Nn * D0 + (size_t)node * 96 + tid] = v;
    }
}

extern "C" void kernel_launch(void* const* d_in, const int* in_sizes, int n_in,
                              void* d_out, int out_size) {
    const float* f0   = (const float*)d_in[0];
    const float* f1   = (const float*)d_in[1];
    const int*   nbr  = (const int*)d_in[2];
    const unsigned char* msk = (const unsigned char*)d_in[3];
    const float* rdist= (const float*)d_in[4];
    const float* We1  = (const float*)d_in[5];
    const float* be1  = (const float*)d_in[6];
    const float* We2  = (const float*)d_in[7];
    const float* be2  = (const float*)d_in[8];
    const float* Wh1  = (const float*)d_in[9];
    const float* bh1  = (const float*)d_in[10];
    const float* Wh2  = (const float*)d_in[11];
    const float* bh2  = (const float*)d_in[12];
    const float* Wn1  = (const float*)d_in[13];
    const float* bn1  = (const float*)d_in[14];
    const float* Wn2  = (const float*)d_in[15];
    const float* bn2  = (const float*)d_in[16];
    const float* Wg   = (const float*)d_in[17];
    const float* bg   = (const float*)d_in[18];
    const float* lng  = (const float*)d_in[19];
    const float* lnb  = (const float*)d_in[20];
    const float* hns  = (const float*)d_in[21];
    const float* hnb  = (const float*)d_in[22];
    float* out = (float*)d_out;

    proj_kernel<<<NT / 16, 256>>>(f0, We1, be1);

    const size_t smem_floats =
        (size_t)AREG + 32 * H1P + 32 * MSP + W1P + 32 * MSP + 32 * 33 + 192 +
        64 + 96 + 32 + 96 + 128 + 64 + 32 + 32 + 2 + 32;
    const size_t smem_bytes = smem_floats * sizeof(float);

    cudaFuncSetAttribute(egnn_main, cudaFuncAttributeMaxDynamicSharedMemorySize,
                         (int)smem_bytes);

    egnn_main<<<NT, 256, smem_bytes>>>(
        f0, f1, nbr, msk, rdist, We1,
        We2, be2, Wh1, bh1, Wh2, bh2,
        Wn1, bn1, Wn2, bn2, Wg, bg, lng, lnb, hns, hnb, out);
}

// round 5
// speedup vs baseline: 1.6961x; 1.1704x over previous
#include <cuda_runtime.h>
#include <math.h>

#define Bb 2
#define Nn 4096
#define NT (Bb*Nn)
#define Kk 32
#define D0 64
#define E2C 322
#define W1P 352
#define H1P 324
#define MSP 36
#define ASZ 4224      // staging buffer A (floats): max(11*352, 128*32, 4096)

__device__ float PI_g[(size_t)NT * E2C + 384];
__device__ float PJ_g[(size_t)NT * E2C + 384];

__device__ __forceinline__ float siluf(float x) { return x / (1.f + __expf(-x)); }
__device__ __forceinline__ float sigmf(float x) { return 1.f / (1.f + __expf(-x)); }

// ---------------- per-node projections: PI = nodes @ We1[0:64] + be1, PJ = nodes @ We1[64:128]
__global__ void __launch_bounds__(256)
proj_kernel(const float* __restrict__ f0, const float* __restrict__ We1,
            const float* __restrict__ be1)
{
    __shared__ float nd[16][65];
    const int nb = blockIdx.x * 16;
    const int tid = threadIdx.x;
    for (int idx = tid; idx < 16 * 64; idx += 256)
        nd[idx >> 6][idx & 63] = f0[(size_t)nb * 64 + idx];
    __syncthreads();
    for (int idx = tid; idx < 16 * E2C; idx += 256) {
        const int n = idx / E2C;
        const int c = idx - n * E2C;
        float si = 0.f, sj = 0.f;
        #pragma unroll 8
        for (int d = 0; d < 64; d++) {
            const float v = nd[n][d];
            si += v * __ldg(&We1[d * E2C + c]);
            sj += v * __ldg(&We1[(64 + d) * E2C + c]);
        }
        PI_g[(size_t)(nb + n) * E2C + c] = si + be1[c];
        PJ_g[(size_t)(nb + n) * E2C + c] = sj;
    }
}

// ---------------- main fused kernel: one block per node, ~70KB smem -> 3 blocks/SM
__global__ void __launch_bounds__(256)
egnn_main(const float* __restrict__ f0, const float* __restrict__ f1,
          const int* __restrict__ nbr, const unsigned char* __restrict__ msk,
          const float* __restrict__ rdist,
          const float* __restrict__ We1,
          const float* __restrict__ We2, const float* __restrict__ be2,
          const float* __restrict__ Wh1, const float* __restrict__ bh1,
          const float* __restrict__ Wh2, const float* __restrict__ bh2,
          const float* __restrict__ Wn1, const float* __restrict__ bn1,
          const float* __restrict__ Wn2, const float* __restrict__ bn2,
          const float* __restrict__ Wg,  const float* __restrict__ bg,
          const float* __restrict__ lng, const float* __restrict__ lnb,
          const float* __restrict__ hns, const float* __restrict__ hnb,
          float* __restrict__ out)
{
    extern __shared__ float sm[];
    float* A       = sm;                       // ASZ: rotating weight stage
    float* H1      = A + ASZ;                  // [32][324]; later aliased by G1 [32][136]
    float* EIc     = H1 + 32 * H1P;            // [32][36]
    float* PI      = EIc + 32 * MSP;           // [352]
    float* MS      = PI + W1P;                 // [32][36]; later aliased by WS
    float* HT2     = MS + 32 * MSP;            // [192]
    float* nodes_s = HT2 + 192;                // [64]
    float* f1i_s   = nodes_s + 64;             // [96]
    float* MI      = f1i_s + 96;               // [32]
    float* NI      = MI + 32;                  // [96]
    float* N1s     = NI + 96;                  // [128]
    float* nouts   = N1s + 128;                // [64]
    float* gates   = nouts + 64;               // [32]
    float* maskv   = gates + 32;               // [32]
    float* stats   = maskv + 32;               // [2]
    int*   nbr_s   = (int*)(stats + 2);        // [32]
    float* G1      = H1;                       // alias (H1 dead after GEMM2)
    float* WS      = MS;                       // alias (MS dead after GEMM3+MI)
    const int G1P  = 136;

    const int tid  = threadIdx.x;
    const int lane = tid & 31;
    const int wrow = tid >> 5;
    const int node = blockIdx.x;
    const int bbase = (node / Nn) * Nn;

    // ---- init: node-i features, PI, GEMM1 weight stage 0 (We1 rows 128..138) ----
    if (tid < 64)           nodes_s[tid]    = f0[(size_t)node * 64 + tid];
    else if (tid < 160)     f1i_s[tid - 64] = f1[(size_t)node * 96 + (tid - 64)];
    for (int c = tid; c < W1P; c += 256)
        PI[c] = (c < E2C) ? PI_g[(size_t)node * E2C + c] : 0.f;
    for (int idx = tid; idx < 11 * W1P; idx += 256) {
        const int r = idx / W1P, c = idx - r * W1P;
        A[idx] = (c < E2C) ? __ldg(&We1[(size_t)(128 + r) * E2C + c]) : 0.f;
    }
    // edge gather
    #pragma unroll
    for (int i = 0; i < 4; i++) {
        const int e = wrow + 8 * i;
        const int j = nbr[node * Kk + e];
        const float* f1j = f1 + (size_t)(bbase + j) * 96;
        const float r0 = f1i_s[lane * 3 + 0] - f1j[lane * 3 + 0];   // NOTE: f1i_s may not be
        const float r1 = f1i_s[lane * 3 + 1] - f1j[lane * 3 + 1];   // visible yet -> must read f1 directly
        const float r2 = f1i_s[lane * 3 + 2] - f1j[lane * 3 + 2];
        (void)r0; (void)r1; (void)r2;
        if (lane == 0) nbr_s[e] = j;
    }
    __syncthreads();
    // rel_norm gather (after sync so f1i_s is valid)
    #pragma unroll
    for (int i = 0; i < 4; i++) {
        const int e = wrow + 8 * i;
        const float* f1j = f1 + (size_t)(bbase + nbr_s[e]) * 96;
        const float r0 = f1i_s[lane * 3 + 0] - f1j[lane * 3 + 0];
        const float r1 = f1i_s[lane * 3 + 1] - f1j[lane * 3 + 1];
        const float r2 = f1i_s[lane * 3 + 2] - f1j[lane * 3 + 2];
        EIc[e * MSP + lane] = sqrtf(r0 * r0 + r1 * r1 + r2 * r2);
        if (lane == 0) {
            EIc[e * MSP + 32] = rdist[node * Kk + e];
            maskv[e] = (float)msk[node * Kk + e];
        }
    }
    // LN stats (warp 7, independent of edges)
    if (wrow == 7) {
        float x0 = nodes_s[lane], x1 = nodes_s[lane + 32];
        float s = x0 + x1, ss = x0 * x0 + x1 * x1;
        #pragma unroll
        for (int o = 16; o > 0; o >>= 1) {
            s  += __shfl_down_sync(0xffffffffu, s,  o);
            ss += __shfl_down_sync(0xffffffffu, ss, o);
        }
        if (lane == 0) {
            const float mu  = s * (1.f / 64.f);
            const float var = ss * (1.f / 64.f) - mu * mu;
            stats[0] = mu;
            stats[1] = rsqrtf(var + 1e-5f);
        }
    }
    __syncthreads();

    // ---- GEMM1 (K=33, 3 staged chunks of 11 rows) ----
    float acc[4][11];
    #pragma unroll
    for (int i = 0; i < 4; i++)
        #pragma unroll
        for (int jj = 0; jj < 11; jj++) acc[i][jj] = 0.f;

    #pragma unroll
    for (int s = 0; s < 3; s++) {
        const int k0 = 11 * s;
        #pragma unroll
        for (int kr = 0; kr < 11; kr++) {
            const int k = k0 + kr;
            const float ev0 = EIc[(wrow +  0) * MSP + k];
            const float ev1 = EIc[(wrow +  8) * MSP + k];
            const float ev2 = EIc[(wrow + 16) * MSP + k];
            const float ev3 = EIc[(wrow + 24) * MSP + k];
            #pragma unroll
            for (int jj = 0; jj < 11; jj++) {
                const float wv = A[kr * W1P + lane + 32 * jj];
                acc[0][jj] += ev0 * wv;
                acc[1][jj] += ev1 * wv;
                acc[2][jj] += ev2 * wv;
                acc[3][jj] += ev3 * wv;
            }
        }
        __syncthreads();
        if (s < 2) {
            for (int idx = tid; idx < 11 * W1P; idx += 256) {
                const int r = idx / W1P, c = idx - r * W1P;
                A[idx] = (c < E2C) ? __ldg(&We1[(size_t)(128 + 11 * (s + 1) + r) * E2C + c]) : 0.f;
            }
            __syncthreads();
        }
    }

    // ---- epilogue (PI + PJ gather + silu -> H1), overlapped with We2 stage 0 ----
    #pragma unroll
    for (int i = 0; i < 4; i++) {
        const int e = wrow + 8 * i;
        const float* pj = PJ_g + (size_t)(bbase + nbr_s[e]) * E2C;
        #pragma unroll
        for (int jj = 0; jj < 11; jj++) {
            const int c = lane + 32 * jj;
            if (c < E2C)
                H1[e * H1P + c] = siluf(acc[i][jj] + PI[c] + __ldg(pj + c));
        }
    }
    {
        const float4* src = (const float4*)We2;
        float4* dst = (float4*)A;
        for (int idx = tid; idx < 1024; idx += 256)
            dst[idx] = __ldg(&src[idx]);
    }
    __syncthreads();

    // ---- GEMM2 (K=322, 3 staged chunks: 128,128,66) ----
    {
        float a2[4] = {0.f, 0.f, 0.f, 0.f};
        #pragma unroll
        for (int s = 0; s < 3; s++) {
            const int r0 = s * 128;
            const int nr = (s < 2) ? 128 : 66;
            const int nr4 = nr & ~3;
            for (int rr = 0; rr < nr4; rr += 4) {
                const float w0 = A[(rr + 0) * 32 + lane];
                const float w1 = A[(rr + 1) * 32 + lane];
                const float w2 = A[(rr + 2) * 32 + lane];
                const float w3 = A[(rr + 3) * 32 + lane];
                #pragma unroll
                for (int i = 0; i < 4; i++) {
                    const float4 h = *(const float4*)&H1[(wrow + 8 * i) * H1P + r0 + rr];
                    a2[i] += h.x * w0 + h.y * w1 + h.z * w2 + h.w * w3;
                }
            }
            for (int rr = nr4; rr < nr; rr++) {
                const float wv = A[rr * 32 + lane];
                #pragma unroll
                for (int i = 0; i < 4; i++)
                    a2[i] += H1[(wrow + 8 * i) * H1P + r0 + rr] * wv;
            }
            __syncthreads();
            if (s < 2) {
                const int n0 = (s + 1) * 128;
                const int nn = (s == 0) ? 128 : 66;
                const float4* src = (const float4*)(We2 + n0 * 32);
                float4* dst = (float4*)A;
                for (int idx = tid; idx < nn * 8; idx += 256)
                    dst[idx] = __ldg(&src[idx]);
                __syncthreads();
            }
        }
        #pragma unroll
        for (int i = 0; i < 4; i++)
            MS[(wrow + 8 * i) * MSP + lane] = siluf(a2[i] + be2[lane]);
    }
    __syncthreads();

    // ---- stage Wh1 (warps 0-6) + MI from MS (warp 7) ----
    if (wrow < 7) {
        const float4* src = (const float4*)Wh1;
        float4* dst = (float4*)A;
        for (int idx = tid; idx < 1024; idx += 224)
            dst[idx] = __ldg(&src[idx]);
    } else {
        float s = 0.f;
        #pragma unroll 8
        for (int e = 0; e < 32; e++)
            s += maskv[e] * MS[e * MSP + lane];
        MI[lane] = s;
    }
    __syncthreads();

    // ---- GEMM3: G1[32][128] = silu(MS @ Wh1s + bh1)  (G1 aliases dead H1) ----
    {
        float a3[4][4];
        #pragma unroll
        for (int i = 0; i < 4; i++)
            #pragma unroll
            for (int jj = 0; jj < 4; jj++) a3[i][jj] = 0.f;
        #pragma unroll 4
        for (int r = 0; r < 32; r++) {
            const float mv0 = MS[(wrow +  0) * MSP + r];
            const float mv1 = MS[(wrow +  8) * MSP + r];
            const float mv2 = MS[(wrow + 16) * MSP + r];
            const float mv3 = MS[(wrow + 24) * MSP + r];
            #pragma unroll
            for (int jj = 0; jj < 4; jj++) {
                const float wv = A[r * 128 + lane + 32 * jj];
                a3[0][jj] += mv0 * wv;
                a3[1][jj] += mv1 * wv;
                a3[2][jj] += mv2 * wv;
                a3[3][jj] += mv3 * wv;
            }
        }
        __syncthreads();   // MS reads done (WS will alias), A reads done
        #pragma unroll
        for (int i = 0; i < 4; i++)
            #pragma unroll
            for (int jj = 0; jj < 4; jj++) {
                const int c = lane + 32 * jj;
                G1[(wrow + 8 * i) * G1P + c] = siluf(a3[i][jj] + bh1[c]);
            }
    }
    // stage Wh2 into A (A reads finished at the sync above)
    {
        const float4* src = (const float4*)Wh2;
        float4* dst = (float4*)A;
        for (int idx = tid; idx < 1024; idx += 256)
            dst[idx] = __ldg(&src[idx]);
    }
    __syncthreads();

    // ---- GEMM4: WS[32][32] = G1 @ Wh2s + bh2  (WS aliases MS region) ----
    {
        float a4[4] = {0.f, 0.f, 0.f, 0.f};
        for (int r = 0; r < 128; r += 4) {
            const float w0 = A[(r + 0) * 32 + lane];
            const float w1 = A[(r + 1) * 32 + lane];
            const float w2 = A[(r + 2) * 32 + lane];
            const float w3 = A[(r + 3) * 32 + lane];
            #pragma unroll
            for (int i = 0; i < 4; i++) {
                const float4 g = *(const float4*)&G1[(wrow + 8 * i) * G1P + r];
                a4[i] += g.x * w0 + g.y * w1 + g.z * w2 + g.w * w3;
            }
        }
        #pragma unroll
        for (int i = 0; i < 4; i++)
            WS[(wrow + 8 * i) * MSP + lane] = a4[i] + bh2[lane];
    }
    __syncthreads();

    // ---- htype_update (warps 0-5, two e-halves), NI prep (warps 6-7) ----
    if (tid < 192) {
        const int half = (tid >= 96);
        const int t = tid - 96 * half;
        const int d = t / 3;
        const float hs = hns[d], hb = hnb[d];
        const float fi = f1i_s[t];
        const int e0 = half * 16;
        float s = 0.f;
        #pragma unroll 4
        for (int e = e0; e < e0 + 16; e++) {
            const float nrm  = EIc[e * MSP + d];
            const float coef = __fdividef(nrm * hs + hb, fmaxf(nrm, 1e-8f));
            const float relv = fi - __ldg(&f1[(size_t)(bbase + nbr_s[e]) * 96 + t]);
            s += relv * coef * WS[e * MSP + d];
        }
        HT2[tid] = s;
    } else if (tid < 192 + 64) {
        const int c = tid - 192;
        NI[c] = (nodes_s[c] - stats[0]) * stats[1] * lng[c] + lnb[c];
        if (c < 32) NI[64 + c] = MI[c];
    }
    __syncthreads();

    // ---- N1[128] = silu(node_in @ Wn1 + bn1) ----
    if (tid < 128) {
        float a = 0.f;
        #pragma unroll 8
        for (int r = 0; r < 96; r++) a += NI[r] * __ldg(&Wn1[r * 128 + tid]);
        N1s[tid] = siluf(a + bn1[tid]);
    }
    __syncthreads();

    // ---- node_out[64] = N1 @ Wn2 + bn2 + nodes ----
    if (tid < 64) {
        float a = 0.f;
        #pragma unroll 8
        for (int r = 0; r < 128; r++) a += N1s[r] * __ldg(&Wn2[r * 64 + tid]);
        const float v = a + bn2[tid] + nodes_s[tid];
        nouts[tid] = v;
        out[(size_t)node * 64 + tid] = v;
    }
    __syncthreads();

    // ---- gate[32] = sigmoid(node_out @ Wg + bg) ----
    if (tid < 32) {
        float a = 0.f;
        #pragma unroll 8
        for (int r = 0; r < 64; r++) a += nouts[r] * __ldg(&Wg[r * 32 + tid]);
        gates[tid] = sigmf(a + bg[tid]);
    }
    __syncthreads();

    // ---- f1_out = (features1 + htype_update) * gate ----
    if (tid < 96) {
        const int d = tid / 3;
        const float v = (f1i_s[tid] + HT2[tid] + HT2[96 + tid]) * gates[d];
        out[(size_t)Bb * Nn * D0 + (size_t)node * 96 + tid] = v;
    }
}

extern "C" void kernel_launch(void* const* d_in, const int* in_sizes, int n_in,
                              void* d_out, int out_size) {
    const float* f0   = (const float*)d_in[0];
    const float* f1   = (const float*)d_in[1];
    const int*   nbr  = (const int*)d_in[2];
    const unsigned char* msk = (const unsigned char*)d_in[3];
    const float* rdist= (const float*)d_in[4];
    const float* We1  = (const float*)d_in[5];
    const float* be1  = (const float*)d_in[6];
    const float* We2  = (const float*)d_in[7];
    const float* be2  = (const float*)d_in[8];
    const float* Wh1  = (const float*)d_in[9];
    const float* bh1  = (const float*)d_in[10];
    const float* Wh2  = (const float*)d_in[11];
    const float* bh2  = (const float*)d_in[12];
    const float* Wn1  = (const float*)d_in[13];
    const float* bn1  = (const float*)d_in[14];
    const float* Wn2  = (const float*)d_in[15];
    const float* bn2  = (const float*)d_in[16];
    const float* Wg   = (const float*)d_in[17];
    const float* bg   = (const float*)d_in[18];
    const float* lng  = (const float*)d_in[19];
    const float* lnb  = (const float*)d_in[20];
    const float* hns  = (const float*)d_in[21];
    const float* hnb  = (const float*)d_in[22];
    float* out = (float*)d_out;

    proj_kernel<<<NT / 16, 256>>>(f0, We1, be1);

    const size_t smem_floats =
        (size_t)ASZ + 32 * H1P + 32 * MSP + W1P + 32 * MSP + 192 +
        64 + 96 + 32 + 96 + 128 + 64 + 32 + 32 + 2 + 32;
    const size_t smem_bytes = smem_floats * sizeof(float);

    cudaFuncSetAttribute(egnn_main, cudaFuncAttributeMaxDynamicSharedMemorySize,
                         (int)smem_bytes);

    egnn_main<<<NT, 256, smem_bytes>>>(
        f0, f1, nbr, msk, rdist, We1,
        We2, be2, Wh1, bh1, Wh2, bh2,
        Wn1, bn1, Wn2, bn2, Wg, bg, lng, lnb, hns, hnb, out);
}